// round 1
// baseline (speedup 1.0000x reference)
#include <cuda_runtime.h>
#include <math.h>

// Problem constants
#define BB 8
#define AA 64
#define HH 128
#define WW 128
#define HX 120
#define WX 120
#define NY (BB*HH*WW)      // 131072
#define NX (BB*AA*HX*WX)   // 7372800
#define NW (AA*9*9)        // 5184
#define TAUF 0.1f

// ------------------------- device state (static, no allocs) ----------------
__device__ float g_g[NX];          // gradient Dt(R)
__device__ float g_R[NY];          // residual Y - D(X)
__device__ float g_Dpart[8*NY];    // atom-group partial sums of D
__device__ float g_pl1[1024];      // per-block l1 partials
__device__ float g_pfid[128];      // per-block fidelity partials
__device__ float g_cur_cost;
__device__ float g_l1X;
__device__ float g_acc_alpha;
__device__ float g_acc_fid;
__device__ int   g_done;
__device__ unsigned g_count;

// ------------------------- helpers -----------------------------------------
__device__ __forceinline__ float blockReduce(float v, float* sb)
{
    #pragma unroll
    for (int o = 16; o > 0; o >>= 1) v += __shfl_down_sync(0xffffffffu, v, o);
    int lane = threadIdx.x & 31;
    int w    = threadIdx.x >> 5;
    if (lane == 0) sb[w] = v;
    __syncthreads();
    int nw = (blockDim.x + 31) >> 5;
    v = (threadIdx.x < (unsigned)nw) ? sb[threadIdx.x] : 0.f;
    if (w == 0) {
        #pragma unroll
        for (int o = 16; o > 0; o >>= 1) v += __shfl_down_sync(0xffffffffu, v, o);
    }
    __syncthreads();   // allow sb reuse
    return v;          // total valid in thread 0
}

__device__ __forceinline__ float softt(float z, float ta)
{
    float t = fabsf(z) - ta;
    return (t > 0.f) ? copysignf(t, z) : 0.f;
}

// ------------------------- D conv (transposed conv) + l1 -------------------
// Computes partial D(Xu) per atom-group into g_Dpart, plus l1(Xu) partials.
// mode 0: Xu = X (raw, ungated). mode 1: Xu = soft(X + alpha*g, tau*alpha), gated on g_done.
// Grid: 1024 blocks = 8 batch x 16 tiles(32x32) x 8 atom-groups(8 atoms). 128 threads.
__global__ void __launch_bounds__(128) k_conv_d(const float* __restrict__ X,
                                                const float* __restrict__ Wd,
                                                int mode, float alpha)
{
    if (mode && *((volatile int*)&g_done)) return;

    int bid   = blockIdx.x;
    int group = bid & 7;
    int tile  = (bid >> 3) & 15;
    int b     = bid >> 7;
    int p0 = (tile >> 2) * 32;
    int q0 = (tile & 3) * 32;
    int tid = threadIdx.x;
    int row = tid & 31;       // output row within tile
    int cg  = tid >> 5;       // column group (8 cols each)

    __shared__ float s[40 * 41];   // Xu tile with halo, padded stride 41 (conflict-free)
    __shared__ float sb[32];

    float acc[8];
    #pragma unroll
    for (int j = 0; j < 8; j++) acc[j] = 0.f;
    float l1 = 0.f;
    const float ta = TAUF * alpha;

    for (int a = group * 8; a < group * 8 + 8; ++a) {
        const float* Xa = X   + (size_t)(b * AA + a) * (HX * WX);
        const float* Ga = g_g + (size_t)(b * AA + a) * (HX * WX);
        __syncthreads();
        for (int e = tid; e < 1600; e += 128) {
            int r = e / 40, c = e - r * 40;
            int y = p0 - 8 + r, x = q0 - 8 + c;
            float v = 0.f;
            if ((unsigned)y < (unsigned)HX && (unsigned)x < (unsigned)WX) {
                float xv = Xa[y * WX + x];
                if (mode) {
                    float z = fmaf(alpha, Ga[y * WX + x], xv);
                    v = softt(z, ta);
                } else {
                    v = xv;
                }
            }
            s[r * 41 + c] = v;
        }
        __syncthreads();

        // l1 over owned (non-halo) region: global (p0+row, q0+cg*8+j) clipped to X domain
        if (p0 + row < HX) {
            #pragma unroll
            for (int j = 0; j < 8; j++) {
                int xx = q0 + cg * 8 + j;
                if (xx < WX) l1 += fabsf(s[(row + 8) * 41 + cg * 8 + 8 + j]);
            }
        }

        // conv: out(p,q) += sum_{u,v} Wd[a][u][v] * Xu[p-u, q-v]
        const float* w = Wd + a * 81;
        #pragma unroll
        for (int u = 0; u < 9; ++u) {
            float win[16];
            #pragma unroll
            for (int i = 0; i < 16; i++) win[i] = s[(row + 8 - u) * 41 + cg * 8 + i];
            #pragma unroll
            for (int v = 0; v < 9; ++v) {
                float wv = __ldg(w + u * 9 + v);
                #pragma unroll
                for (int j = 0; j < 8; j++) acc[j] = fmaf(wv, win[8 - v + j], acc[j]);
            }
        }
    }

    float* dp = g_Dpart + (size_t)group * NY + (size_t)b * (HH * WW)
              + (p0 + row) * WW + q0 + cg * 8;
    #pragma unroll
    for (int j = 0; j < 8; j++) dp[j] = acc[j];

    float tot = blockReduce(l1, sb);
    if (tid == 0) g_pl1[bid] = tot;
}

// ------------------------- residual + cost + accept ------------------------
// mode 0 (INIT): current_cost = ||R||^2 + tau*l1(X); stores l1X; done=0.
// mode 1 (CAND k): gated; cost_k = fid + tau*(k==0 ? l1X : l1(Xu)); accept logic.
// Always writes R = Y - D (last writer == accepted candidate).
// Grid: 128 x 256.
__global__ void __launch_bounds__(256) k_reduce2(const float* __restrict__ Y,
                                                 int mode, int k, float alpha)
{
    if (mode && *((volatile int*)&g_done)) return;
    int tid = threadIdx.x;
    float fid = 0.f;
    for (int i = blockIdx.x * 256 + tid; i < NY; i += 128 * 256) {
        float d = 0.f;
        #pragma unroll
        for (int gr = 0; gr < 8; ++gr) d += g_Dpart[(size_t)gr * NY + i];
        float r = Y[i] - d;
        g_R[i] = r;
        fid += r * r;
    }
    __shared__ float sb[32];
    float tot = blockReduce(fid, sb);
    if (tid == 0) g_pfid[blockIdx.x] = tot;
    __threadfence();
    __shared__ bool last;
    if (tid == 0) last = (atomicAdd(&g_count, 1u) == gridDim.x - 1);
    __syncthreads();
    if (!last) return;

    float f = (tid < 128) ? g_pfid[tid] : 0.f;
    f = blockReduce(f, sb);
    float l = 0.f;
    for (int j = tid; j < 1024; j += 256) l += g_pl1[j];
    l = blockReduce(l, sb);
    if (tid == 0) {
        g_count = 0;
        if (mode == 0) {
            g_cur_cost = f + TAUF * l;
            g_l1X = l;
            g_done = 0;
        } else {
            float cost = f + TAUF * ((k == 0) ? g_l1X : l);
            if (k == 16 || cost < g_cur_cost) {
                g_done = 1;
                g_acc_alpha = alpha;
                g_acc_fid = f;
            }
        }
    }
}

// ------------------------- g = Dt(R) ----------------------------------------
// Dt[b,a,y,x] = sum_{i,j} R[b,y+i,x+j] * Wd[a][j][i]   (spatially transposed weight)
// Grid: 1024 = 8 batch x 16 atom-groups(4) x 4 row-tiles(32) x 2 col-tiles(64). 256 threads.
__global__ void __launch_bounds__(256) k_dt(const float* __restrict__ Wd)
{
    int bid = blockIdx.x;
    int ct  = bid & 1;
    int rt  = (bid >> 1) & 3;
    int ag  = (bid >> 3) & 15;
    int b   = bid >> 7;
    int r0 = rt * 32, q0 = ct * 64;
    int tid = threadIdx.x;
    int row = tid & 31, cg = tid >> 5;

    __shared__ float s[40 * 73];   // R tile with halo, stride 73 (conflict-free)
    const float* Rb = g_R + (size_t)b * (HH * WW);
    for (int e = tid; e < 40 * 72; e += 256) {
        int r = e / 72, c = e - r * 72;
        int rr = r0 + r, cc = q0 + c;
        s[r * 73 + c] = (rr < HH && cc < WW) ? Rb[rr * WW + cc] : 0.f;
    }
    __syncthreads();

    int y  = r0 + row;
    int x0 = q0 + cg * 8;
    bool valid = (y < HX) && (x0 < WX);

    for (int a = ag * 4; a < ag * 4 + 4; ++a) {
        float acc[8];
        #pragma unroll
        for (int j = 0; j < 8; j++) acc[j] = 0.f;
        const float* w = Wd + a * 81;
        #pragma unroll
        for (int i = 0; i < 9; ++i) {
            float win[16];
            #pragma unroll
            for (int m = 0; m < 16; m++) win[m] = s[(row + i) * 73 + cg * 8 + m];
            #pragma unroll
            for (int j = 0; j < 9; ++j) {
                float wv = __ldg(w + j * 9 + i);   // transposed access
                #pragma unroll
                for (int jj = 0; jj < 8; jj++) acc[jj] = fmaf(wv, win[jj + j], acc[jj]);
            }
        }
        if (valid) {
            float* go = g_g + ((size_t)(b * AA + a) * HX + y) * WX + x0;
            #pragma unroll
            for (int jj = 0; jj < 8; jj++) go[jj] = acc[jj];
        }
    }
}

// ------------------------- apply accepted step ------------------------------
// X_dst = soft(X_src + acc_alpha*g, tau*acc_alpha); computes l1(X_new);
// sets current_cost for next linesearch (fid stored at acceptance) and resets done.
// Grid: 1024 x 256.
__global__ void __launch_bounds__(256) k_apply(const float* __restrict__ Xsrc,
                                               float* __restrict__ Xdst)
{
    float alpha = g_acc_alpha;
    float ta = TAUF * alpha;
    float l1 = 0.f;
    int tid = threadIdx.x;
    for (int i = blockIdx.x * 256 + tid; i < NX; i += 1024 * 256) {
        float z = fmaf(alpha, g_g[i], Xsrc[i]);
        float t = fabsf(z) - ta;
        float v = (t > 0.f) ? copysignf(t, z) : 0.f;
        Xdst[i] = v;
        l1 += (t > 0.f) ? t : 0.f;
    }
    __shared__ float sb[32];
    float tot = blockReduce(l1, sb);
    if (tid == 0) g_pl1[blockIdx.x] = tot;
    __threadfence();
    __shared__ bool last;
    if (tid == 0) last = (atomicAdd(&g_count, 1u) == gridDim.x - 1);
    __syncthreads();
    if (!last) return;
    float l = 0.f;
    for (int j = tid; j < 1024; j += 256) l += g_pl1[j];
    l = blockReduce(l, sb);
    if (tid == 0) {
        g_count = 0;
        g_cur_cost = g_acc_fid + TAUF * l;
        g_l1X = l;
        g_done = 0;
    }
}

// ------------------------- host launcher ------------------------------------
extern "C" void kernel_launch(void* const* d_in, const int* in_sizes, int n_in,
                              void* d_out, int out_size)
{
    const float* Y  = nullptr;
    const float* X1 = nullptr;
    const float* Wd = nullptr;
    for (int i = 0; i < n_in; i++) {
        if (in_sizes[i] == NY)      Y  = (const float*)d_in[i];
        else if (in_sizes[i] == NX) X1 = (const float*)d_in[i];
        else if (in_sizes[i] == NW) Wd = (const float*)d_in[i];
    }
    if (!Y)  Y  = (const float*)d_in[0];
    if (!X1) X1 = (const float*)d_in[1];
    if (!Wd) Wd = (const float*)d_in[2];

    float* X = (float*)d_out;

    for (int ls = 0; ls < 4; ++ls) {
        const float* Xin = (ls == 0) ? X1 : X;
        if (ls == 0) {
            // init: R = Y - D(X), current_cost = ||R||^2 + tau*l1(X)
            k_conv_d<<<1024, 128>>>(Xin, Wd, 0, 0.f);
            k_reduce2<<<128, 256>>>(Y, 0, -1, 0.f);
        }
        // gradient
        k_dt<<<1024, 256>>>(Wd);
        // linesearch candidates (gated on device; skipped after acceptance)
        for (int k = 0; k <= 16; ++k) {
            float alpha = ldexpf(1.0f, -k);
            k_conv_d<<<1024, 128>>>(Xin, Wd, 1, alpha);
            k_reduce2<<<128, 256>>>(Y, 1, k, alpha);
        }
        // apply accepted step; prepares next linesearch's current_cost/done
        k_apply<<<1024, 256>>>(Xin, X);
    }
}

// round 2
// speedup vs baseline: 1.1905x; 1.1905x over previous
#include <cuda_runtime.h>
#include <math.h>

// Problem constants
#define BB 8
#define AA 64
#define HH 128
#define WW 128
#define HX 120
#define WX 120
#define NY (BB*HH*WW)      // 131072
#define NX (BB*AA*HX*WX)   // 7372800
#define NW (AA*9*9)        // 5184
#define TAUF 0.1f
#define NY4 (NY/4)         // 32768
#define NX4 (NX/4)         // 1843200

// ------------------------- device state (static, no allocs) ----------------
__device__ float g_g[NX];          // gradient Dt(R)
__device__ float g_R0[NY];         // residual candidate 0
__device__ float g_R1[NY];         // residual candidate 1
__device__ float g_Dpart[16*NY];   // atom-group partial D planes (2 candidates x 8 groups)
__device__ float g_pl1a[1024];
__device__ float g_pl1b[1024];
__device__ float g_pfa[128];
__device__ float g_pfb[128];
__device__ float g_cur_cost;
__device__ float g_l1X;
__device__ float g_acc_alpha;
__device__ float g_acc_fid;
__device__ int   g_done;
__device__ int   g_rsel;
__device__ unsigned g_count;

// ------------------------- helpers -----------------------------------------
__device__ __forceinline__ float blockReduce(float v, float* sb)
{
    #pragma unroll
    for (int o = 16; o > 0; o >>= 1) v += __shfl_down_sync(0xffffffffu, v, o);
    int lane = threadIdx.x & 31;
    int w    = threadIdx.x >> 5;
    if (lane == 0) sb[w] = v;
    __syncthreads();
    int nw = (blockDim.x + 31) >> 5;
    v = (threadIdx.x < (unsigned)nw) ? sb[threadIdx.x] : 0.f;
    if (w == 0) {
        #pragma unroll
        for (int o = 16; o > 0; o >>= 1) v += __shfl_down_sync(0xffffffffu, v, o);
    }
    __syncthreads();
    return v;   // valid in thread 0
}

__device__ __forceinline__ float softt(float z, float ta)
{
    float t = fabsf(z) - ta;
    return (t > 0.f) ? copysignf(t, z) : 0.f;
}

// ------------------------- D conv (transposed conv) + l1 -------------------
// NC=1: single candidate (planes 0..7). NC=2: pair (planes 0..7 and 8..15).
// MODE=0: raw X (init, ungated). MODE=1: Xu = soft(X + a*g, tau*a), gated.
// Grid: 1024 = 8 batch x 16 tiles(32x32) x 8 atom-groups(8 atoms). 128 threads.
template<int NC, int MODE>
__global__ void __launch_bounds__(128, 7) k_conv(const float* __restrict__ X,
                                                 const float* __restrict__ Wd,
                                                 float a0, float a1)
{
    if (MODE && *((volatile int*)&g_done)) return;

    int bid   = blockIdx.x;
    int group = bid & 7;
    int tile  = (bid >> 3) & 15;
    int b     = bid >> 7;
    int p0 = (tile >> 2) * 32;
    int q0 = (tile & 3) * 32;
    int tid = threadIdx.x;
    int row = tid & 31;
    int cg  = tid >> 5;

    __shared__ float s0[40 * 41];
    __shared__ float s1[(NC == 2) ? 40 * 41 : 1];
    __shared__ float sb[32];

    float acc0[8], acc1[8];
    #pragma unroll
    for (int j = 0; j < 8; j++) { acc0[j] = 0.f; acc1[j] = 0.f; }
    float l10 = 0.f, l11 = 0.f;
    const float ta0 = TAUF * a0;
    const float ta1 = TAUF * a1;

    for (int a = group * 8; a < group * 8 + 8; ++a) {
        const float* Xa = X   + (size_t)(b * AA + a) * (HX * WX);
        const float* Ga = g_g + (size_t)(b * AA + a) * (HX * WX);
        __syncthreads();
        #pragma unroll
        for (int i = 0; i < 13; i++) {
            int e = tid + i * 128;
            if (e < 1600) {
                int r = e / 40, c = e - r * 40;
                int y = p0 - 8 + r, x = q0 - 8 + c;
                float v0 = 0.f, v1 = 0.f;
                if ((unsigned)y < (unsigned)HX && (unsigned)x < (unsigned)WX) {
                    float xv = Xa[y * WX + x];
                    if (MODE) {
                        float gv = Ga[y * WX + x];
                        v0 = softt(fmaf(a0, gv, xv), ta0);
                        if (NC == 2) v1 = softt(fmaf(a1, gv, xv), ta1);
                    } else {
                        v0 = xv;
                    }
                }
                s0[r * 41 + c] = v0;
                if (NC == 2) s1[r * 41 + c] = v1;
            }
        }
        __syncthreads();

        // l1 over owned (non-halo) region clipped to X domain
        if (p0 + row < HX) {
            #pragma unroll
            for (int j = 0; j < 8; j++) {
                if (q0 + cg * 8 + j < WX) {
                    int si = (row + 8) * 41 + cg * 8 + 8 + j;
                    l10 += fabsf(s0[si]);
                    if (NC == 2) l11 += fabsf(s1[si]);
                }
            }
        }

        const float* w = Wd + a * 81;
        #pragma unroll
        for (int u = 0; u < 9; ++u) {
            float wrow[9];
            #pragma unroll
            for (int v = 0; v < 9; ++v) wrow[v] = __ldg(w + u * 9 + v);
            float win[16];
            #pragma unroll
            for (int i = 0; i < 16; i++) win[i] = s0[(row + 8 - u) * 41 + cg * 8 + i];
            #pragma unroll
            for (int v = 0; v < 9; ++v) {
                #pragma unroll
                for (int j = 0; j < 8; j++) acc0[j] = fmaf(wrow[v], win[8 - v + j], acc0[j]);
            }
            if (NC == 2) {
                #pragma unroll
                for (int i = 0; i < 16; i++) win[i] = s1[(row + 8 - u) * 41 + cg * 8 + i];
                #pragma unroll
                for (int v = 0; v < 9; ++v) {
                    #pragma unroll
                    for (int j = 0; j < 8; j++) acc1[j] = fmaf(wrow[v], win[8 - v + j], acc1[j]);
                }
            }
        }
    }

    size_t off = ((size_t)b * (HH * WW) + (p0 + row) * WW + q0 + cg * 8) >> 2;
    float4* dp0 = (float4*)(g_Dpart) + (size_t)group * NY4 + off;
    dp0[0] = make_float4(acc0[0], acc0[1], acc0[2], acc0[3]);
    dp0[1] = make_float4(acc0[4], acc0[5], acc0[6], acc0[7]);
    if (NC == 2) {
        float4* dp1 = (float4*)(g_Dpart) + (size_t)(8 + group) * NY4 + off;
        dp1[0] = make_float4(acc1[0], acc1[1], acc1[2], acc1[3]);
        dp1[1] = make_float4(acc1[4], acc1[5], acc1[6], acc1[7]);
    }

    float t0 = blockReduce(l10, sb);
    if (tid == 0) g_pl1a[bid] = t0;
    if (NC == 2) {
        float t1 = blockReduce(l11, sb);
        if (tid == 0) g_pl1b[bid] = t1;
    }
}

// ------------------------- residual + cost + accept ------------------------
// Grid: 128 x 256 (one float4 per thread over NY).
// mode 0 (INIT): current_cost = fid + tau*l1(X); l1X; done=0; rsel=0.
// mode 1: gated; candidate k (and k+1 if NC==2). k==0 cost uses l1X (faithful).
template<int NC>
__global__ void __launch_bounds__(256) k_red(const float* __restrict__ Y,
                                             int mode, int k, float a0, float a1)
{
    if (mode && *((volatile int*)&g_done)) return;
    int tid = threadIdx.x;
    int i4  = blockIdx.x * 256 + tid;       // exactly covers NY4

    const float4* Y4 = (const float4*)Y;
    const float4* DP = (const float4*)g_Dpart;
    float4 y = Y4[i4];

    float4 d0 = make_float4(0.f, 0.f, 0.f, 0.f);
    #pragma unroll
    for (int gr = 0; gr < 8; ++gr) {
        float4 p = DP[(size_t)gr * NY4 + i4];
        d0.x += p.x; d0.y += p.y; d0.z += p.z; d0.w += p.w;
    }
    float4 r0 = make_float4(y.x - d0.x, y.y - d0.y, y.z - d0.z, y.w - d0.w);
    ((float4*)g_R0)[i4] = r0;
    float fid0 = r0.x * r0.x + r0.y * r0.y + r0.z * r0.z + r0.w * r0.w;

    float fid1 = 0.f;
    if (NC == 2) {
        float4 d1 = make_float4(0.f, 0.f, 0.f, 0.f);
        #pragma unroll
        for (int gr = 8; gr < 16; ++gr) {
            float4 p = DP[(size_t)gr * NY4 + i4];
            d1.x += p.x; d1.y += p.y; d1.z += p.z; d1.w += p.w;
        }
        float4 r1 = make_float4(y.x - d1.x, y.y - d1.y, y.z - d1.z, y.w - d1.w);
        ((float4*)g_R1)[i4] = r1;
        fid1 = r1.x * r1.x + r1.y * r1.y + r1.z * r1.z + r1.w * r1.w;
    }

    __shared__ float sb[32];
    float t = blockReduce(fid0, sb);
    if (tid == 0) g_pfa[blockIdx.x] = t;
    if (NC == 2) {
        t = blockReduce(fid1, sb);
        if (tid == 0) g_pfb[blockIdx.x] = t;
    }
    __threadfence();
    __shared__ bool last;
    if (tid == 0) last = (atomicAdd(&g_count, 1u) == gridDim.x - 1);
    __syncthreads();
    if (!last) return;

    float f0 = (tid < 128) ? g_pfa[tid] : 0.f;
    f0 = blockReduce(f0, sb);
    float f1 = 0.f;
    if (NC == 2) {
        f1 = (tid < 128) ? g_pfb[tid] : 0.f;
        f1 = blockReduce(f1, sb);
    }
    float la = 0.f, lb = 0.f;
    for (int j = tid; j < 1024; j += 256) {
        la += g_pl1a[j];
        if (NC == 2) lb += g_pl1b[j];
    }
    la = blockReduce(la, sb);
    if (NC == 2) lb = blockReduce(lb, sb);

    if (tid == 0) {
        g_count = 0;
        if (mode == 0) {
            g_cur_cost = f0 + TAUF * la;
            g_l1X = la;
            g_done = 0;
            g_rsel = 0;
        } else {
            float c0 = f0 + TAUF * ((k == 0) ? g_l1X : la);
            if (k == 16 || c0 < g_cur_cost) {
                g_done = 1; g_rsel = 0; g_acc_alpha = a0; g_acc_fid = f0;
            } else if (NC == 2) {
                float c1 = f1 + TAUF * lb;
                if ((k + 1 == 16) || c1 < g_cur_cost) {
                    g_done = 1; g_rsel = 1; g_acc_alpha = a1; g_acc_fid = f1;
                }
            }
        }
    }
}

// ------------------------- g = Dt(R) ----------------------------------------
// Dt[b,a,y,x] = sum_{i,j} R[b,y+i,x+j] * Wd[a][j][i]
// Grid: 1024 = 8 batch x 16 atom-groups(4) x 4 row-tiles(32) x 2 col-tiles(64).
__global__ void __launch_bounds__(256) k_dt(const float* __restrict__ Wd)
{
    int bid = blockIdx.x;
    int ct  = bid & 1;
    int rt  = (bid >> 1) & 3;
    int ag  = (bid >> 3) & 15;
    int b   = bid >> 7;
    int r0 = rt * 32, q0 = ct * 64;
    int tid = threadIdx.x;
    int row = tid & 31, cg = tid >> 5;

    __shared__ float s[40 * 73];
    const float* Rb = (g_rsel ? g_R1 : g_R0) + (size_t)b * (HH * WW);
    for (int e = tid; e < 40 * 72; e += 256) {
        int r = e / 72, c = e - r * 72;
        int rr = r0 + r, cc = q0 + c;
        s[r * 73 + c] = (rr < HH && cc < WW) ? Rb[rr * WW + cc] : 0.f;
    }
    __syncthreads();

    int y  = r0 + row;
    int x0 = q0 + cg * 8;
    bool valid = (y < HX) && (x0 < WX);

    for (int a = ag * 4; a < ag * 4 + 4; ++a) {
        float acc[8];
        #pragma unroll
        for (int j = 0; j < 8; j++) acc[j] = 0.f;
        const float* w = Wd + a * 81;
        #pragma unroll
        for (int i = 0; i < 9; ++i) {
            float win[16];
            #pragma unroll
            for (int m = 0; m < 16; m++) win[m] = s[(row + i) * 73 + cg * 8 + m];
            #pragma unroll
            for (int j = 0; j < 9; ++j) {
                float wv = __ldg(w + j * 9 + i);
                #pragma unroll
                for (int jj = 0; jj < 8; jj++) acc[jj] = fmaf(wv, win[jj + j], acc[jj]);
            }
        }
        if (valid) {
            float* go = g_g + ((size_t)(b * AA + a) * HX + y) * WX + x0;
            #pragma unroll
            for (int jj = 0; jj < 8; jj++) go[jj] = acc[jj];
        }
    }
}

// ------------------------- apply accepted step ------------------------------
__global__ void __launch_bounds__(256) k_apply(const float* __restrict__ Xsrc,
                                               float* __restrict__ Xdst)
{
    float alpha = g_acc_alpha;
    float ta = TAUF * alpha;
    float l1 = 0.f;
    int tid = threadIdx.x;
    const float4* Xs4 = (const float4*)Xsrc;
    const float4* G4  = (const float4*)g_g;
    float4* Xd4 = (float4*)Xdst;
    for (int i = blockIdx.x * 256 + tid; i < NX4; i += 1024 * 256) {
        float4 x = Xs4[i];
        float4 g = G4[i];
        float4 o;
        {
            float z = fmaf(alpha, g.x, x.x); float t = fabsf(z) - ta;
            o.x = (t > 0.f) ? copysignf(t, z) : 0.f; l1 += (t > 0.f) ? t : 0.f;
        }
        {
            float z = fmaf(alpha, g.y, x.y); float t = fabsf(z) - ta;
            o.y = (t > 0.f) ? copysignf(t, z) : 0.f; l1 += (t > 0.f) ? t : 0.f;
        }
        {
            float z = fmaf(alpha, g.z, x.z); float t = fabsf(z) - ta;
            o.z = (t > 0.f) ? copysignf(t, z) : 0.f; l1 += (t > 0.f) ? t : 0.f;
        }
        {
            float z = fmaf(alpha, g.w, x.w); float t = fabsf(z) - ta;
            o.w = (t > 0.f) ? copysignf(t, z) : 0.f; l1 += (t > 0.f) ? t : 0.f;
        }
        Xd4[i] = o;
    }
    __shared__ float sb[32];
    float tot = blockReduce(l1, sb);
    if (tid == 0) g_pl1a[blockIdx.x] = tot;
    __threadfence();
    __shared__ bool last;
    if (tid == 0) last = (atomicAdd(&g_count, 1u) == gridDim.x - 1);
    __syncthreads();
    if (!last) return;
    float l = 0.f;
    for (int j = tid; j < 1024; j += 256) l += g_pl1a[j];
    l = blockReduce(l, sb);
    if (tid == 0) {
        g_count = 0;
        g_cur_cost = g_acc_fid + TAUF * l;
        g_l1X = l;
        g_done = 0;
    }
}

// ------------------------- host launcher ------------------------------------
extern "C" void kernel_launch(void* const* d_in, const int* in_sizes, int n_in,
                              void* d_out, int out_size)
{
    const float* Y  = nullptr;
    const float* X1 = nullptr;
    const float* Wd = nullptr;
    for (int i = 0; i < n_in; i++) {
        if (in_sizes[i] == NY)      Y  = (const float*)d_in[i];
        else if (in_sizes[i] == NX) X1 = (const float*)d_in[i];
        else if (in_sizes[i] == NW) Wd = (const float*)d_in[i];
    }
    if (!Y)  Y  = (const float*)d_in[0];
    if (!X1) X1 = (const float*)d_in[1];
    if (!Wd) Wd = (const float*)d_in[2];

    float* X = (float*)d_out;

    for (int ls = 0; ls < 4; ++ls) {
        const float* Xin = (ls == 0) ? X1 : X;
        if (ls == 0) {
            k_conv<1, 0><<<1024, 128>>>(Xin, Wd, 0.f, 0.f);
            k_red<1><<<128, 256>>>(Y, 0, -1, 0.f, 0.f);
        }
        k_dt<<<1024, 256>>>(Wd);
        // paired candidates k = 0..15 (gated on device)
        for (int m = 0; m < 8; ++m) {
            float a0 = ldexpf(1.0f, -2 * m);
            float a1 = ldexpf(1.0f, -2 * m - 1);
            k_conv<2, 1><<<1024, 128>>>(Xin, Wd, a0, a1);
            k_red<2><<<128, 256>>>(Y, 1, 2 * m, a0, a1);
        }
        // unconditional fallback candidate k = 16
        {
            float a16 = ldexpf(1.0f, -16);
            k_conv<1, 1><<<1024, 128>>>(Xin, Wd, a16, 0.f);
            k_red<1><<<128, 256>>>(Y, 1, 16, a16, 0.f);
        }
        k_apply<<<1024, 256>>>(Xin, X);
    }
}

// round 3
// speedup vs baseline: 1.2184x; 1.0234x over previous
#include <cuda_runtime.h>
#include <math.h>

#define BB 8
#define AA 64
#define HH 128
#define WW 128
#define HX 120
#define WX 120
#define NY (BB*HH*WW)      // 131072
#define NX (BB*AA*HX*WX)   // 7372800
#define NW (AA*9*9)        // 5184
#define TAUF 0.1f
#define NY4 (NY/4)
#define NX4 (NX/4)
#define SSTR 44            // conv smem stride (44 mod 32 = 12 -> conflict-free f4)
#define DSTR 76            // dt smem stride   (76 mod 32 = 12 -> conflict-free f4)

// ------------------------- device state ------------------------------------
__device__ float g_g[NX];
__device__ float g_R[4*NY];          // residual per candidate lane
__device__ float g_Dpart[16*NY];     // plane = cand*4 + group
__device__ float g_pl1[4*512];
__device__ float g_pf[4*128];
__device__ float g_pl1x[1024];
__device__ float g_cur_cost, g_l1X, g_acc_alpha, g_acc_fid;
__device__ int   g_done, g_rsel;
__device__ unsigned g_count;

// ------------------------- packed f32x2 helpers -----------------------------
__device__ __forceinline__ unsigned long long pk(float lo, float hi)
{
    unsigned long long r;
    asm("mov.b64 %0, {%1, %2};" : "=l"(r) : "f"(lo), "f"(hi));
    return r;
}
__device__ __forceinline__ unsigned long long f2fma(unsigned long long a,
                                                    unsigned long long b,
                                                    unsigned long long c)
{
    unsigned long long d;
    asm("fma.rn.f32x2 %0, %1, %2, %3;" : "=l"(d) : "l"(a), "l"(b), "l"(c));
    return d;
}
__device__ __forceinline__ float2 upk(unsigned long long v)
{
    float2 r;
    asm("mov.b64 {%0, %1}, %2;" : "=f"(r.x), "=f"(r.y) : "l"(v));
    return r;
}

__device__ __forceinline__ float blockReduce(float v, float* sb)
{
    #pragma unroll
    for (int o = 16; o > 0; o >>= 1) v += __shfl_down_sync(0xffffffffu, v, o);
    int lane = threadIdx.x & 31;
    int w    = threadIdx.x >> 5;
    if (lane == 0) sb[w] = v;
    __syncthreads();
    int nw = (blockDim.x + 31) >> 5;
    v = (threadIdx.x < (unsigned)nw) ? sb[threadIdx.x] : 0.f;
    if (w == 0) {
        #pragma unroll
        for (int o = 16; o > 0; o >>= 1) v += __shfl_down_sync(0xffffffffu, v, o);
    }
    __syncthreads();
    return v;
}

__device__ __forceinline__ float softt(float z, float ta)
{
    float t = fabsf(z) - ta;
    return (t > 0.f) ? copysignf(t, z) : 0.f;
}

// ------------------------- D conv (transposed conv) + l1 -------------------
// Grid: 512 = 8 batch x 16 tiles(32x32) x 4 atom-groups(16 atoms). 128 threads.
// MODE=0: Xu = X (ungated, NC must be 1). MODE=1: Xu = soft(X + a_c*g, tau*a_c), gated.
template<int NC, int MODE>
__global__ void __launch_bounds__(128, 4) k_conv(const float* __restrict__ X,
                                                 const float* __restrict__ Wd,
                                                 float a0, float a1, float a2, float a3)
{
    if (MODE && *((volatile int*)&g_done)) return;

    int bid   = blockIdx.x;
    int group = bid & 3;
    int tile  = (bid >> 2) & 15;
    int b     = bid >> 6;
    int p0 = (tile >> 2) * 32;
    int q0 = (tile & 3) * 32;
    int tid = threadIdx.x;
    int row = tid & 31;
    int cg  = tid >> 5;

    __shared__ __align__(16) float s[NC][40 * SSTR];
    __shared__ float sb[32];

    const float al[4] = {a0, a1, a2, a3};
    float ta[NC];
    #pragma unroll
    for (int c = 0; c < NC; c++) ta[c] = TAUF * al[c];

    unsigned long long acc[NC][4];
    #pragma unroll
    for (int c = 0; c < NC; c++)
        #pragma unroll
        for (int j = 0; j < 4; j++) acc[c][j] = 0ull;
    float l1[NC];
    #pragma unroll
    for (int c = 0; c < NC; c++) l1[c] = 0.f;

    for (int a = group * 16; a < group * 16 + 16; ++a) {
        const float* Xa = X   + (size_t)(b * AA + a) * (HX * WX);
        const float* Ga = g_g + (size_t)(b * AA + a) * (HX * WX);
        __syncthreads();
        #pragma unroll
        for (int i = 0; i < 13; i++) {
            int e = tid + i * 128;
            if (e < 1600) {
                int r = e / 40, c0 = e - r * 40;
                int y = p0 - 8 + r, x = q0 - 8 + c0;
                bool in = ((unsigned)y < (unsigned)HX) && ((unsigned)x < (unsigned)WX);
                bool own = in && (r >= 8) && (c0 >= 8);
                float xv = 0.f, gv = 0.f;
                if (in) {
                    xv = Xa[y * WX + x];
                    if (MODE) gv = Ga[y * WX + x];
                }
                #pragma unroll
                for (int c = 0; c < NC; c++) {
                    float v;
                    if (MODE) v = in ? softt(fmaf(al[c], gv, xv), ta[c]) : 0.f;
                    else      v = xv;
                    s[c][r * SSTR + c0] = v;
                    if (own) l1[c] += fabsf(v);
                }
            }
        }
        __syncthreads();

        const float* w = Wd + a * 81;
        #pragma unroll 3
        for (int u = 0; u < 9; ++u) {
            unsigned long long wv2[9];
            #pragma unroll
            for (int v = 0; v < 9; ++v) {
                float wv = __ldg(w + u * 9 + v);
                wv2[v] = pk(wv, wv);
            }
            #pragma unroll
            for (int c = 0; c < NC; c++) {
                const float4* sp4 = (const float4*)(s[c] + (row + 8 - u) * SSTR + cg * 8);
                float4 A = sp4[0], B4 = sp4[1], C4 = sp4[2], D4 = sp4[3];
                float win[16] = {A.x, A.y, A.z, A.w, B4.x, B4.y, B4.z, B4.w,
                                 C4.x, C4.y, C4.z, C4.w, D4.x, D4.y, D4.z, D4.w};
                unsigned long long P[15];
                #pragma unroll
                for (int t = 0; t < 15; t++) P[t] = pk(win[t], win[t + 1]);
                #pragma unroll
                for (int v = 0; v < 9; ++v) {
                    #pragma unroll
                    for (int jp = 0; jp < 4; ++jp)
                        acc[c][jp] = f2fma(wv2[v], P[8 - v + 2 * jp], acc[c][jp]);
                }
            }
        }
    }

    size_t off = ((size_t)b * (HH * WW) + (p0 + row) * WW + q0 + cg * 8) >> 2;
    #pragma unroll
    for (int c = 0; c < NC; c++) {
        float2 p0v = upk(acc[c][0]), p1v = upk(acc[c][1]);
        float2 p2v = upk(acc[c][2]), p3v = upk(acc[c][3]);
        float4* dp = (float4*)(g_Dpart) + (size_t)(c * 4 + group) * NY4 + off;
        dp[0] = make_float4(p0v.x, p0v.y, p1v.x, p1v.y);
        dp[1] = make_float4(p2v.x, p2v.y, p3v.x, p3v.y);
    }
    #pragma unroll
    for (int c = 0; c < NC; c++) {
        float t = blockReduce(l1[c], sb);
        if (tid == 0) g_pl1[c * 512 + bid] = t;
    }
}

// ------------------------- residual + cost + accept ------------------------
// Grid: 128 x 256. mode 0 = INIT, mode 1 = candidates k..k+NC-1 (gated).
template<int NC>
__global__ void __launch_bounds__(256) k_red(const float* __restrict__ Y,
                                             int mode, int k,
                                             float a0, float a1, float a2, float a3)
{
    if (mode && *((volatile int*)&g_done)) return;
    int tid = threadIdx.x;
    int i4  = blockIdx.x * 256 + tid;

    const float4* Y4 = (const float4*)Y;
    const float4* DP = (const float4*)g_Dpart;
    float4 y = Y4[i4];

    float fid[NC];
    #pragma unroll
    for (int c = 0; c < NC; c++) {
        float4 d = make_float4(0.f, 0.f, 0.f, 0.f);
        #pragma unroll
        for (int gr = 0; gr < 4; ++gr) {
            float4 p = DP[(size_t)(c * 4 + gr) * NY4 + i4];
            d.x += p.x; d.y += p.y; d.z += p.z; d.w += p.w;
        }
        float4 r = make_float4(y.x - d.x, y.y - d.y, y.z - d.z, y.w - d.w);
        ((float4*)(g_R + (size_t)c * NY))[i4] = r;
        fid[c] = r.x * r.x + r.y * r.y + r.z * r.z + r.w * r.w;
    }

    __shared__ float sb[32];
    #pragma unroll
    for (int c = 0; c < NC; c++) {
        float t = blockReduce(fid[c], sb);
        if (tid == 0) g_pf[c * 128 + blockIdx.x] = t;
    }
    __threadfence();
    __shared__ bool last;
    if (tid == 0) last = (atomicAdd(&g_count, 1u) == gridDim.x - 1);
    __syncthreads();
    if (!last) return;

    float f[NC], l[NC];
    #pragma unroll
    for (int c = 0; c < NC; c++) {
        float v = (tid < 128) ? g_pf[c * 128 + tid] : 0.f;
        f[c] = blockReduce(v, sb);
        float lv = 0.f;
        for (int j = tid; j < 512; j += 256) lv += g_pl1[c * 512 + j];
        l[c] = blockReduce(lv, sb);
    }

    if (tid == 0) {
        g_count = 0;
        if (mode == 0) {
            g_cur_cost = f[0] + TAUF * l[0];
            g_l1X = l[0];
            g_done = 0;
            g_rsel = 0;
        } else {
            const float al[4] = {a0, a1, a2, a3};
            #pragma unroll
            for (int c = 0; c < NC; c++) {
                float cost = f[c] + TAUF * ((k + c == 0) ? g_l1X : l[c]);
                if ((k + c == 16) || cost < g_cur_cost) {
                    g_done = 1; g_rsel = c;
                    g_acc_alpha = al[c]; g_acc_fid = f[c];
                    break;
                }
            }
        }
    }
}

// ------------------------- g = Dt(R) ----------------------------------------
// Grid: 1024 = 8 batch x 16 atom-groups(4) x 4 row-tiles x 2 col-tiles. 256 thr.
__global__ void __launch_bounds__(256, 3) k_dt(const float* __restrict__ Wd)
{
    int bid = blockIdx.x;
    int ct  = bid & 1;
    int rt  = (bid >> 1) & 3;
    int ag  = (bid >> 3) & 15;
    int b   = bid >> 7;
    int r0 = rt * 32, q0 = ct * 64;
    int tid = threadIdx.x;
    int row = tid & 31, cg = tid >> 5;

    __shared__ __align__(16) float s[40 * DSTR];
    const float* Rb = g_R + (size_t)g_rsel * NY + (size_t)b * (HH * WW);
    for (int e = tid; e < 40 * 72; e += 256) {
        int r = e / 72, c = e - r * 72;
        int rr = r0 + r, cc = q0 + c;
        s[r * DSTR + c] = (rr < HH && cc < WW) ? Rb[rr * WW + cc] : 0.f;
    }
    __syncthreads();

    int y  = r0 + row;
    int x0 = q0 + cg * 8;
    bool valid = (y < HX) && (x0 < WX);

    for (int a = ag * 4; a < ag * 4 + 4; ++a) {
        unsigned long long acc[4];
        #pragma unroll
        for (int jp = 0; jp < 4; jp++) acc[jp] = 0ull;
        const float* w = Wd + a * 81;
        #pragma unroll 3
        for (int i = 0; i < 9; ++i) {
            unsigned long long wv2[9];
            #pragma unroll
            for (int j = 0; j < 9; ++j) {
                float wv = __ldg(w + j * 9 + i);   // transposed weight
                wv2[j] = pk(wv, wv);
            }
            const float4* sp4 = (const float4*)(s + (row + i) * DSTR + cg * 8);
            float4 A = sp4[0], B4 = sp4[1], C4 = sp4[2], D4 = sp4[3];
            float win[16] = {A.x, A.y, A.z, A.w, B4.x, B4.y, B4.z, B4.w,
                             C4.x, C4.y, C4.z, C4.w, D4.x, D4.y, D4.z, D4.w};
            unsigned long long P[15];
            #pragma unroll
            for (int t = 0; t < 15; t++) P[t] = pk(win[t], win[t + 1]);
            #pragma unroll
            for (int j = 0; j < 9; ++j) {
                #pragma unroll
                for (int jp = 0; jp < 4; ++jp)
                    acc[jp] = f2fma(wv2[j], P[j + 2 * jp], acc[jp]);
            }
        }
        if (valid) {
            float* go = g_g + ((size_t)(b * AA + a) * HX + y) * WX + x0;
            #pragma unroll
            for (int jp = 0; jp < 4; jp++) {
                float2 p = upk(acc[jp]);
                go[2 * jp] = p.x;
                go[2 * jp + 1] = p.y;
            }
        }
    }
}

// ------------------------- apply accepted step ------------------------------
__global__ void __launch_bounds__(256) k_apply(const float* __restrict__ Xsrc,
                                               float* __restrict__ Xdst)
{
    float alpha = g_acc_alpha;
    float ta = TAUF * alpha;
    float l1 = 0.f;
    int tid = threadIdx.x;
    const float4* Xs4 = (const float4*)Xsrc;
    const float4* G4  = (const float4*)g_g;
    float4* Xd4 = (float4*)Xdst;
    for (int i = blockIdx.x * 256 + tid; i < NX4; i += 1024 * 256) {
        float4 x = Xs4[i];
        float4 g = G4[i];
        float4 o;
        { float z = fmaf(alpha, g.x, x.x); float t = fabsf(z) - ta;
          o.x = (t > 0.f) ? copysignf(t, z) : 0.f; l1 += (t > 0.f) ? t : 0.f; }
        { float z = fmaf(alpha, g.y, x.y); float t = fabsf(z) - ta;
          o.y = (t > 0.f) ? copysignf(t, z) : 0.f; l1 += (t > 0.f) ? t : 0.f; }
        { float z = fmaf(alpha, g.z, x.z); float t = fabsf(z) - ta;
          o.z = (t > 0.f) ? copysignf(t, z) : 0.f; l1 += (t > 0.f) ? t : 0.f; }
        { float z = fmaf(alpha, g.w, x.w); float t = fabsf(z) - ta;
          o.w = (t > 0.f) ? copysignf(t, z) : 0.f; l1 += (t > 0.f) ? t : 0.f; }
        Xd4[i] = o;
    }
    __shared__ float sb[32];
    float tot = blockReduce(l1, sb);
    if (tid == 0) g_pl1x[blockIdx.x] = tot;
    __threadfence();
    __shared__ bool last;
    if (tid == 0) last = (atomicAdd(&g_count, 1u) == gridDim.x - 1);
    __syncthreads();
    if (!last) return;
    float l = 0.f;
    for (int j = tid; j < 1024; j += 256) l += g_pl1x[j];
    l = blockReduce(l, sb);
    if (tid == 0) {
        g_count = 0;
        g_cur_cost = g_acc_fid + TAUF * l;
        g_l1X = l;
        g_done = 0;
    }
}

// ------------------------- host launcher ------------------------------------
extern "C" void kernel_launch(void* const* d_in, const int* in_sizes, int n_in,
                              void* d_out, int out_size)
{
    const float* Y  = nullptr;
    const float* X1 = nullptr;
    const float* Wd = nullptr;
    for (int i = 0; i < n_in; i++) {
        if (in_sizes[i] == NY)      Y  = (const float*)d_in[i];
        else if (in_sizes[i] == NX) X1 = (const float*)d_in[i];
        else if (in_sizes[i] == NW) Wd = (const float*)d_in[i];
    }
    if (!Y)  Y  = (const float*)d_in[0];
    if (!X1) X1 = (const float*)d_in[1];
    if (!Wd) Wd = (const float*)d_in[2];

    float* X = (float*)d_out;

    for (int ls = 0; ls < 4; ++ls) {
        const float* Xin = (ls == 0) ? X1 : X;
        if (ls == 0) {
            k_conv<1, 0><<<512, 128>>>(Xin, Wd, 0.f, 0.f, 0.f, 0.f);
            k_red<1><<<128, 256>>>(Y, 0, -1, 0.f, 0.f, 0.f, 0.f);
        }
        k_dt<<<1024, 256>>>(Wd);
        // quad candidates k = 4m .. 4m+3 (gated on device)
        for (int m = 0; m < 4; ++m) {
            float a0 = ldexpf(1.0f, -(4 * m));
            float a1 = ldexpf(1.0f, -(4 * m + 1));
            float a2 = ldexpf(1.0f, -(4 * m + 2));
            float a3 = ldexpf(1.0f, -(4 * m + 3));
            k_conv<4, 1><<<512, 128>>>(Xin, Wd, a0, a1, a2, a3);
            k_red<4><<<128, 256>>>(Y, 1, 4 * m, a0, a1, a2, a3);
        }
        // unconditional fallback candidate k = 16
        {
            float a16 = ldexpf(1.0f, -16);
            k_conv<1, 1><<<512, 128>>>(Xin, Wd, a16, 0.f, 0.f, 0.f);
            k_red<1><<<128, 256>>>(Y, 1, 16, a16, 0.f, 0.f, 0.f);
        }
        k_apply<<<1024, 256>>>(Xin, X);
    }
}

// round 4
// speedup vs baseline: 1.3896x; 1.1405x over previous
#include <cuda_runtime.h>
#include <math.h>

#define BB 8
#define AA 64
#define HH 128
#define WW 128
#define HX 120
#define WX 120
#define NY (BB*HH*WW)      // 131072
#define NX (BB*AA*HX*WX)   // 7372800
#define NW (AA*9*9)        // 5184
#define TAUF 0.1f
#define NY4 (NY/4)
#define NX4 (NX/4)
#define S2   42            // conv smem stride in float2 units (84 words, mod32=20: conflict-free)
#define DSTR 76            // dt smem stride (floats)

// ------------------------- device state ------------------------------------
__device__ float g_g[NX];
__device__ float g_R[4*NY];           // residual per candidate lane
__device__ float g_Dpart[32*NY];      // plane = cand*8 + group
__device__ float g_pl1[4*1024];
__device__ float g_pf[4*128];
__device__ float g_pl1x[1024];
__device__ float g_cur_cost, g_l1X, g_acc_alpha, g_acc_fid;
__device__ int   g_done, g_rsel;
__device__ unsigned g_count;

// ------------------------- packed f32x2 helpers -----------------------------
__device__ __forceinline__ unsigned long long pk(float lo, float hi)
{
    unsigned long long r;
    asm("mov.b64 %0, {%1, %2};" : "=l"(r) : "f"(lo), "f"(hi));
    return r;
}
__device__ __forceinline__ unsigned long long f2fma(unsigned long long a,
                                                    unsigned long long b,
                                                    unsigned long long c)
{
    unsigned long long d;
    asm("fma.rn.f32x2 %0, %1, %2, %3;" : "=l"(d) : "l"(a), "l"(b), "l"(c));
    return d;
}
__device__ __forceinline__ float2 upk(unsigned long long v)
{
    float2 r;
    asm("mov.b64 {%0, %1}, %2;" : "=f"(r.x), "=f"(r.y) : "l"(v));
    return r;
}

__device__ __forceinline__ float blockReduce(float v, float* sb)
{
    #pragma unroll
    for (int o = 16; o > 0; o >>= 1) v += __shfl_down_sync(0xffffffffu, v, o);
    int lane = threadIdx.x & 31;
    int w    = threadIdx.x >> 5;
    if (lane == 0) sb[w] = v;
    __syncthreads();
    int nw = (blockDim.x + 31) >> 5;
    v = (threadIdx.x < (unsigned)nw) ? sb[threadIdx.x] : 0.f;
    if (w == 0) {
        #pragma unroll
        for (int o = 16; o > 0; o >>= 1) v += __shfl_down_sync(0xffffffffu, v, o);
    }
    __syncthreads();
    return v;
}

__device__ __forceinline__ float softt(float z, float ta)
{
    float t = fabsf(z) - ta;
    return (t > 0.f) ? copysignf(t, z) : 0.f;
}

// ------------------------- quad-candidate D conv + l1 -----------------------
// Candidates interleaved pairwise in smem: s[p][pos] = float2(cand_{2p}, cand_{2p+1}).
// Inner-loop f2fma operand is a direct LDS.128 — no packing movs.
// Grid: 1024 = 8 batch x 16 tiles(32x32) x 8 atom-groups(8 atoms). 128 threads.
__global__ void __launch_bounds__(128, 5) k_conv4(const float* __restrict__ X,
                                                  const float* __restrict__ Wd,
                                                  float a0, float a1, float a2, float a3)
{
    if (*((volatile int*)&g_done)) return;

    int bid   = blockIdx.x;
    int group = bid & 7;
    int tile  = (bid >> 3) & 15;
    int b     = bid >> 7;
    int p0 = (tile >> 2) * 32;
    int q0 = (tile & 3) * 32;
    int tid = threadIdx.x;
    int row = tid & 31;
    int cg  = tid >> 5;

    __shared__ __align__(16) float2 s[2][40 * S2];
    __shared__ float sb[32];

    const float al[4] = {a0, a1, a2, a3};
    const float ta[4] = {TAUF * a0, TAUF * a1, TAUF * a2, TAUF * a3};

    unsigned long long acc[2][8];
    #pragma unroll
    for (int p = 0; p < 2; p++)
        #pragma unroll
        for (int j = 0; j < 8; j++) acc[p][j] = 0ull;
    float l1[4] = {0.f, 0.f, 0.f, 0.f};

    for (int a = group * 8; a < group * 8 + 8; ++a) {
        const float* Xa = X   + (size_t)(b * AA + a) * (HX * WX);
        const float* Ga = g_g + (size_t)(b * AA + a) * (HX * WX);
        __syncthreads();
        #pragma unroll
        for (int i = 0; i < 13; i++) {
            int e = tid + i * 128;
            if (e < 1600) {
                int r = e / 40, c0 = e - r * 40;
                int y = p0 - 8 + r, x = q0 - 8 + c0;
                bool in = ((unsigned)y < (unsigned)HX) && ((unsigned)x < (unsigned)WX);
                float v[4] = {0.f, 0.f, 0.f, 0.f};
                if (in) {
                    float xv = Xa[y * WX + x];
                    float gv = Ga[y * WX + x];
                    #pragma unroll
                    for (int c = 0; c < 4; c++) v[c] = softt(fmaf(al[c], gv, xv), ta[c]);
                    if (r >= 8 && c0 >= 8) {
                        #pragma unroll
                        for (int c = 0; c < 4; c++) l1[c] += fabsf(v[c]);
                    }
                }
                s[0][r * S2 + c0] = make_float2(v[0], v[1]);
                s[1][r * S2 + c0] = make_float2(v[2], v[3]);
            }
        }
        __syncthreads();

        const float* w = Wd + a * 81;
        #pragma unroll 1
        for (int u = 0; u < 9; ++u) {
            unsigned long long wv2[9];
            #pragma unroll
            for (int v = 0; v < 9; ++v) {
                float wv = __ldg(w + u * 9 + v);
                wv2[v] = pk(wv, wv);
            }
            #pragma unroll
            for (int p = 0; p < 2; p++) {
                const ulonglong2* sp = (const ulonglong2*)(s[p] + (row + 8 - u) * S2 + cg * 8);
                unsigned long long win2[16];
                #pragma unroll
                for (int i = 0; i < 8; i++) {
                    ulonglong2 q = sp[i];
                    win2[2 * i]     = q.x;
                    win2[2 * i + 1] = q.y;
                }
                #pragma unroll
                for (int v = 0; v < 9; ++v) {
                    #pragma unroll
                    for (int j = 0; j < 8; ++j)
                        acc[p][j] = f2fma(wv2[v], win2[8 - v + j], acc[p][j]);
                }
            }
        }
    }

    size_t off = ((size_t)b * (HH * WW) + (p0 + row) * WW + q0 + cg * 8) >> 2;
    #pragma unroll
    for (int p = 0; p < 2; p++) {
        float2 e[8];
        #pragma unroll
        for (int j = 0; j < 8; j++) e[j] = upk(acc[p][j]);
        float4* dpa = (float4*)(g_Dpart) + (size_t)((2 * p) * 8 + group) * NY4 + off;
        dpa[0] = make_float4(e[0].x, e[1].x, e[2].x, e[3].x);
        dpa[1] = make_float4(e[4].x, e[5].x, e[6].x, e[7].x);
        float4* dpb = (float4*)(g_Dpart) + (size_t)((2 * p + 1) * 8 + group) * NY4 + off;
        dpb[0] = make_float4(e[0].y, e[1].y, e[2].y, e[3].y);
        dpb[1] = make_float4(e[4].y, e[5].y, e[6].y, e[7].y);
    }
    #pragma unroll
    for (int c = 0; c < 4; c++) {
        float t = blockReduce(l1[c], sb);
        if (tid == 0) g_pl1[c * 1024 + bid] = t;
    }
}

// ------------------------- scalar single-candidate conv ---------------------
// MODE 0: raw X (init, ungated). MODE 1: gated candidate (k=16 fallback).
// Writes planes group 0..7 of candidate 0.
template<int MODE>
__global__ void __launch_bounds__(128, 7) k_conv1(const float* __restrict__ X,
                                                  const float* __restrict__ Wd,
                                                  float a0)
{
    if (MODE && *((volatile int*)&g_done)) return;

    int bid   = blockIdx.x;
    int group = bid & 7;
    int tile  = (bid >> 3) & 15;
    int b     = bid >> 7;
    int p0 = (tile >> 2) * 32;
    int q0 = (tile & 3) * 32;
    int tid = threadIdx.x;
    int row = tid & 31;
    int cg  = tid >> 5;

    __shared__ float s[40 * 41];
    __shared__ float sb[32];

    float acc[8];
    #pragma unroll
    for (int j = 0; j < 8; j++) acc[j] = 0.f;
    float l1 = 0.f;
    const float ta0 = TAUF * a0;

    for (int a = group * 8; a < group * 8 + 8; ++a) {
        const float* Xa = X   + (size_t)(b * AA + a) * (HX * WX);
        const float* Ga = g_g + (size_t)(b * AA + a) * (HX * WX);
        __syncthreads();
        for (int e = tid; e < 1600; e += 128) {
            int r = e / 40, c = e - r * 40;
            int y = p0 - 8 + r, x = q0 - 8 + c;
            float v = 0.f;
            if ((unsigned)y < (unsigned)HX && (unsigned)x < (unsigned)WX) {
                float xv = Xa[y * WX + x];
                if (MODE) v = softt(fmaf(a0, Ga[y * WX + x], xv), ta0);
                else      v = xv;
                if (r >= 8 && c >= 8) l1 += fabsf(v);
            }
            s[r * 41 + c] = v;
        }
        __syncthreads();

        const float* w = Wd + a * 81;
        #pragma unroll
        for (int u = 0; u < 9; ++u) {
            float win[16];
            #pragma unroll
            for (int i = 0; i < 16; i++) win[i] = s[(row + 8 - u) * 41 + cg * 8 + i];
            #pragma unroll
            for (int v = 0; v < 9; ++v) {
                float wv = __ldg(w + u * 9 + v);
                #pragma unroll
                for (int j = 0; j < 8; j++) acc[j] = fmaf(wv, win[8 - v + j], acc[j]);
            }
        }
    }

    size_t off = ((size_t)b * (HH * WW) + (p0 + row) * WW + q0 + cg * 8) >> 2;
    float4* dp = (float4*)(g_Dpart) + (size_t)group * NY4 + off;
    dp[0] = make_float4(acc[0], acc[1], acc[2], acc[3]);
    dp[1] = make_float4(acc[4], acc[5], acc[6], acc[7]);

    float t = blockReduce(l1, sb);
    if (tid == 0) g_pl1[bid] = t;
}

// ------------------------- residual + cost + accept ------------------------
// Grid: 128 x 256. mode 0 = INIT, mode 1 = candidates k..k+NC-1 (gated).
template<int NC>
__global__ void __launch_bounds__(256) k_red(const float* __restrict__ Y,
                                             int mode, int k,
                                             float a0, float a1, float a2, float a3)
{
    if (mode && *((volatile int*)&g_done)) return;
    int tid = threadIdx.x;
    int i4  = blockIdx.x * 256 + tid;

    const float4* Y4 = (const float4*)Y;
    const float4* DP = (const float4*)g_Dpart;
    float4 y = Y4[i4];

    float fid[NC];
    #pragma unroll
    for (int c = 0; c < NC; c++) {
        float4 d = make_float4(0.f, 0.f, 0.f, 0.f);
        #pragma unroll
        for (int gr = 0; gr < 8; ++gr) {
            float4 p = DP[(size_t)(c * 8 + gr) * NY4 + i4];
            d.x += p.x; d.y += p.y; d.z += p.z; d.w += p.w;
        }
        float4 r = make_float4(y.x - d.x, y.y - d.y, y.z - d.z, y.w - d.w);
        ((float4*)(g_R + (size_t)c * NY))[i4] = r;
        fid[c] = r.x * r.x + r.y * r.y + r.z * r.z + r.w * r.w;
    }

    __shared__ float sb[32];
    #pragma unroll
    for (int c = 0; c < NC; c++) {
        float t = blockReduce(fid[c], sb);
        if (tid == 0) g_pf[c * 128 + blockIdx.x] = t;
    }
    __threadfence();
    __shared__ bool last;
    if (tid == 0) last = (atomicAdd(&g_count, 1u) == gridDim.x - 1);
    __syncthreads();
    if (!last) return;

    float f[NC], l[NC];
    #pragma unroll
    for (int c = 0; c < NC; c++) {
        float v = (tid < 128) ? g_pf[c * 128 + tid] : 0.f;
        f[c] = blockReduce(v, sb);
        float lv = 0.f;
        for (int j = tid; j < 1024; j += 256) lv += g_pl1[c * 1024 + j];
        l[c] = blockReduce(lv, sb);
    }

    if (tid == 0) {
        g_count = 0;
        if (mode == 0) {
            g_cur_cost = f[0] + TAUF * l[0];
            g_l1X = l[0];
            g_done = 0;
            g_rsel = 0;
        } else {
            const float al[4] = {a0, a1, a2, a3};
            #pragma unroll
            for (int c = 0; c < NC; c++) {
                float cost = f[c] + TAUF * ((k + c == 0) ? g_l1X : l[c]);
                if ((k + c == 16) || cost < g_cur_cost) {
                    g_done = 1; g_rsel = c;
                    g_acc_alpha = al[c]; g_acc_fid = f[c];
                    break;
                }
            }
        }
    }
}

// ------------------------- g = Dt(R) ----------------------------------------
// Loop-swapped: window packed once per i-row, shared across 4 atoms (f32x2 accs).
// Grid: 1024 = 8 batch x 16 atom-groups(4) x 4 row-tiles x 2 col-tiles. 256 thr.
__global__ void __launch_bounds__(256, 2) k_dt(const float* __restrict__ Wd)
{
    int bid = blockIdx.x;
    int ct  = bid & 1;
    int rt  = (bid >> 1) & 3;
    int ag  = (bid >> 3) & 15;
    int b   = bid >> 7;
    int r0 = rt * 32, q0 = ct * 64;
    int tid = threadIdx.x;
    int row = tid & 31, cg = tid >> 5;

    __shared__ __align__(16) float s[40 * DSTR];
    const float* Rb = g_R + (size_t)g_rsel * NY + (size_t)b * (HH * WW);
    for (int e = tid; e < 40 * 72; e += 256) {
        int r = e / 72, c = e - r * 72;
        int rr = r0 + r, cc = q0 + c;
        s[r * DSTR + c] = (rr < HH && cc < WW) ? Rb[rr * WW + cc] : 0.f;
    }
    __syncthreads();

    int y  = r0 + row;
    int x0 = q0 + cg * 8;
    bool valid = (y < HX) && (x0 < WX);
    int abase = ag * 4;

    unsigned long long acc[4][4];
    #pragma unroll
    for (int a = 0; a < 4; a++)
        #pragma unroll
        for (int jp = 0; jp < 4; jp++) acc[a][jp] = 0ull;

    #pragma unroll 1
    for (int i = 0; i < 9; ++i) {
        const float4* sp4 = (const float4*)(s + (row + i) * DSTR + cg * 8);
        float4 A = sp4[0], B4 = sp4[1], C4 = sp4[2], D4 = sp4[3];
        float win[16] = {A.x, A.y, A.z, A.w, B4.x, B4.y, B4.z, B4.w,
                         C4.x, C4.y, C4.z, C4.w, D4.x, D4.y, D4.z, D4.w};
        unsigned long long P[15];
        #pragma unroll
        for (int t = 0; t < 15; t++) P[t] = pk(win[t], win[t + 1]);
        #pragma unroll
        for (int a = 0; a < 4; a++) {
            const float* w = Wd + (abase + a) * 81;
            #pragma unroll
            for (int j = 0; j < 9; ++j) {
                float wv = __ldg(w + j * 9 + i);   // transposed weight
                unsigned long long wv2 = pk(wv, wv);
                #pragma unroll
                for (int jp = 0; jp < 4; ++jp)
                    acc[a][jp] = f2fma(wv2, P[j + 2 * jp], acc[a][jp]);
            }
        }
    }
    if (valid) {
        #pragma unroll
        for (int a = 0; a < 4; a++) {
            float* go = g_g + ((size_t)(b * AA + abase + a) * HX + y) * WX + x0;
            #pragma unroll
            for (int jp = 0; jp < 4; jp++) {
                float2 p = upk(acc[a][jp]);
                go[2 * jp] = p.x;
                go[2 * jp + 1] = p.y;
            }
        }
    }
}

// ------------------------- apply accepted step ------------------------------
__global__ void __launch_bounds__(256) k_apply(const float* __restrict__ Xsrc,
                                               float* __restrict__ Xdst)
{
    float alpha = g_acc_alpha;
    float ta = TAUF * alpha;
    float l1 = 0.f;
    int tid = threadIdx.x;
    const float4* Xs4 = (const float4*)Xsrc;
    const float4* G4  = (const float4*)g_g;
    float4* Xd4 = (float4*)Xdst;
    for (int i = blockIdx.x * 256 + tid; i < NX4; i += 1024 * 256) {
        float4 x = Xs4[i];
        float4 g = G4[i];
        float4 o;
        { float z = fmaf(alpha, g.x, x.x); float t = fabsf(z) - ta;
          o.x = (t > 0.f) ? copysignf(t, z) : 0.f; l1 += (t > 0.f) ? t : 0.f; }
        { float z = fmaf(alpha, g.y, x.y); float t = fabsf(z) - ta;
          o.y = (t > 0.f) ? copysignf(t, z) : 0.f; l1 += (t > 0.f) ? t : 0.f; }
        { float z = fmaf(alpha, g.z, x.z); float t = fabsf(z) - ta;
          o.z = (t > 0.f) ? copysignf(t, z) : 0.f; l1 += (t > 0.f) ? t : 0.f; }
        { float z = fmaf(alpha, g.w, x.w); float t = fabsf(z) - ta;
          o.w = (t > 0.f) ? copysignf(t, z) : 0.f; l1 += (t > 0.f) ? t : 0.f; }
        Xd4[i] = o;
    }
    __shared__ float sb[32];
    float tot = blockReduce(l1, sb);
    if (tid == 0) g_pl1x[blockIdx.x] = tot;
    __threadfence();
    __shared__ bool last;
    if (tid == 0) last = (atomicAdd(&g_count, 1u) == gridDim.x - 1);
    __syncthreads();
    if (!last) return;
    float l = 0.f;
    for (int j = tid; j < 1024; j += 256) l += g_pl1x[j];
    l = blockReduce(l, sb);
    if (tid == 0) {
        g_count = 0;
        g_cur_cost = g_acc_fid + TAUF * l;
        g_l1X = l;
        g_done = 0;
    }
}

// ------------------------- host launcher ------------------------------------
extern "C" void kernel_launch(void* const* d_in, const int* in_sizes, int n_in,
                              void* d_out, int out_size)
{
    const float* Y  = nullptr;
    const float* X1 = nullptr;
    const float* Wd = nullptr;
    for (int i = 0; i < n_in; i++) {
        if (in_sizes[i] == NY)      Y  = (const float*)d_in[i];
        else if (in_sizes[i] == NX) X1 = (const float*)d_in[i];
        else if (in_sizes[i] == NW) Wd = (const float*)d_in[i];
    }
    if (!Y)  Y  = (const float*)d_in[0];
    if (!X1) X1 = (const float*)d_in[1];
    if (!Wd) Wd = (const float*)d_in[2];

    float* X = (float*)d_out;

    for (int ls = 0; ls < 4; ++ls) {
        const float* Xin = (ls == 0) ? X1 : X;
        if (ls == 0) {
            k_conv1<0><<<1024, 128>>>(Xin, Wd, 0.f);
            k_red<1><<<128, 256>>>(Y, 0, -1, 0.f, 0.f, 0.f, 0.f);
        }
        k_dt<<<1024, 256>>>(Wd);
        // quad candidates k = 4m .. 4m+3 (gated on device)
        for (int m = 0; m < 4; ++m) {
            float a0 = ldexpf(1.0f, -(4 * m));
            float a1 = ldexpf(1.0f, -(4 * m + 1));
            float a2 = ldexpf(1.0f, -(4 * m + 2));
            float a3 = ldexpf(1.0f, -(4 * m + 3));
            k_conv4<<<1024, 128>>>(Xin, Wd, a0, a1, a2, a3);
            k_red<4><<<128, 256>>>(Y, 1, 4 * m, a0, a1, a2, a3);
        }
        // unconditional fallback candidate k = 16
        {
            float a16 = ldexpf(1.0f, -16);
            k_conv1<1><<<1024, 128>>>(Xin, Wd, a16);
            k_red<1><<<128, 256>>>(Y, 1, 16, a16, 0.f, 0.f, 0.f);
        }
        k_apply<<<1024, 256>>>(Xin, X);
    }
}

// round 6
// speedup vs baseline: 1.4845x; 1.0683x over previous
#include <cuda_runtime.h>
#include <math.h>
#include <stdint.h>

#define BB 8
#define AA 64
#define HH 128
#define WW 128
#define HX 120
#define WX 120
#define NY (BB*HH*WW)      // 131072
#define NX (BB*AA*HX*WX)   // 7372800
#define NW (AA*9*9)        // 5184
#define TAUF 0.1f
#define NY4 (NY/4)
#define NX4 (NX/4)
#define S2   42            // conv smem stride in float2 (84 words, mod32=20: conflict-free)
#define DSTR 76            // dt smem stride (floats)

// ------------------------- device state ------------------------------------
__device__ float g_g[NX];
__device__ float g_R[4*NY];           // residual per candidate lane
__device__ float g_Dpart[32*NY];      // plane = cand*8 + group
__device__ float g_pl1[4*1024];
__device__ float g_pf[4*128];
__device__ float g_pl1x[1024];
__device__ float g_cur_cost, g_l1X, g_acc_alpha, g_acc_fid;
__device__ int   g_done, g_rsel;
__device__ unsigned g_count;

// ------------------------- packed f32x2 helpers -----------------------------
__device__ __forceinline__ unsigned long long pk(float lo, float hi)
{
    unsigned long long r;
    asm("mov.b64 %0, {%1, %2};" : "=l"(r) : "f"(lo), "f"(hi));
    return r;
}
__device__ __forceinline__ unsigned long long f2fma(unsigned long long a,
                                                    unsigned long long b,
                                                    unsigned long long c)
{
    unsigned long long d;
    asm("fma.rn.f32x2 %0, %1, %2, %3;" : "=l"(d) : "l"(a), "l"(b), "l"(c));
    return d;
}
__device__ __forceinline__ float2 upk(unsigned long long v)
{
    float2 r;
    asm("mov.b64 {%0, %1}, %2;" : "=f"(r.x), "=f"(r.y) : "l"(v));
    return r;
}

// cp.async 4B with zero-fill when sz==0
__device__ __forceinline__ void cpa4(unsigned int daddr, const float* src, unsigned sz)
{
    asm volatile("cp.async.ca.shared.global [%0], [%1], 4, %2;"
                 :: "r"(daddr), "l"(src), "r"(sz));
}
__device__ __forceinline__ void cpa_commit() { asm volatile("cp.async.commit_group;"); }
__device__ __forceinline__ void cpa_wait()   { asm volatile("cp.async.wait_group 0;"); }

__device__ __forceinline__ unsigned int s2u(const void* p)
{
    unsigned int a;
    asm("{ .reg .u64 t; cvta.to.shared.u64 t, %1; cvt.u32.u64 %0, t; }" : "=r"(a) : "l"(p));
    return a;
}

__device__ __forceinline__ float blockReduce(float v, float* sb)
{
    #pragma unroll
    for (int o = 16; o > 0; o >>= 1) v += __shfl_down_sync(0xffffffffu, v, o);
    int lane = threadIdx.x & 31;
    int w    = threadIdx.x >> 5;
    if (lane == 0) sb[w] = v;
    __syncthreads();
    int nw = (blockDim.x + 31) >> 5;
    v = (threadIdx.x < (unsigned)nw) ? sb[threadIdx.x] : 0.f;
    if (w == 0) {
        #pragma unroll
        for (int o = 16; o > 0; o >>= 1) v += __shfl_down_sync(0xffffffffu, v, o);
    }
    __syncthreads();
    return v;
}

__device__ __forceinline__ float softt(float z, float ta)
{
    float t = fabsf(z) - ta;
    return (t > 0.f) ? copysignf(t, z) : 0.f;
}

// ------------------------- quad-candidate D conv + l1 -----------------------
// cp.async-pipelined: stage raw X/g tile of atom a+1 during compute of atom a.
// Candidates interleaved pairwise in smem; inner f2fma operand = direct LDS.128.
// Grid: 1024 = 8 batch x 16 tiles(32x32) x 8 atom-groups(8 atoms). 128 threads.
__global__ void __launch_bounds__(128, 5) k_conv4(const float* __restrict__ X,
                                                  const float* __restrict__ Wd,
                                                  float a0, float a1, float a2, float a3)
{
    if (*((volatile int*)&g_done)) return;

    int bid   = blockIdx.x;
    int group = bid & 7;
    int tile  = (bid >> 3) & 15;
    int b     = bid >> 7;
    int p0 = (tile >> 2) * 32;
    int q0 = (tile & 3) * 32;
    int tid = threadIdx.x;
    int row = tid & 31;
    int cg  = tid >> 5;

    __shared__ __align__(16) float2 s[2][40 * S2];
    __shared__ __align__(16) float stX[1600];
    __shared__ __align__(16) float stG[1600];
    __shared__ float sb[32];

    const float al[4] = {a0, a1, a2, a3};
    const float ta[4] = {TAUF * a0, TAUF * a1, TAUF * a2, TAUF * a3};

    unsigned long long acc[2][8];
    #pragma unroll
    for (int p = 0; p < 2; p++)
        #pragma unroll
        for (int j = 0; j < 8; j++) acc[p][j] = 0ull;
    float l1[4] = {0.f, 0.f, 0.f, 0.f};

    const int g8 = group * 8;
    const size_t plane = (size_t)HX * WX;
    unsigned int stXa = s2u(stX), stGa = s2u(stG);

    // issue stage for first atom
    {
        const float* Xa = X   + ((size_t)b * AA + g8) * plane;
        const float* Ga = g_g + ((size_t)b * AA + g8) * plane;
        #pragma unroll
        for (int i = 0; i < 13; i++) {
            int e = tid + i * 128;
            if (e < 1600) {
                int r = e / 40, c0 = e - r * 40;
                int y = p0 - 8 + r, x = q0 - 8 + c0;
                bool in = ((unsigned)y < (unsigned)HX) && ((unsigned)x < (unsigned)WX);
                int o = in ? (y * WX + x) : 0;
                unsigned sz = in ? 4u : 0u;
                cpa4(stXa + 4u * e, Xa + o, sz);
                cpa4(stGa + 4u * e, Ga + o, sz);
            }
        }
        cpa_commit();
    }

    for (int a = g8; a < g8 + 8; ++a) {
        cpa_wait();
        __syncthreads();          // staging visible to all; s free (prev compute done)

        // transform: staging -> interleaved candidate buffers + l1
        #pragma unroll
        for (int i = 0; i < 13; i++) {
            int e = tid + i * 128;
            if (e < 1600) {
                int r = e / 40, c0 = e - r * 40;
                float xv = stX[e];
                float gv = stG[e];
                float v[4];
                #pragma unroll
                for (int c = 0; c < 4; c++) v[c] = softt(fmaf(al[c], gv, xv), ta[c]);
                if (r >= 8 && c0 >= 8) {
                    #pragma unroll
                    for (int c = 0; c < 4; c++) l1[c] += fabsf(v[c]);
                }
                s[0][r * S2 + c0] = make_float2(v[0], v[1]);
                s[1][r * S2 + c0] = make_float2(v[2], v[3]);
            }
        }
        __syncthreads();          // transform done: s ready, staging free

        // issue stage for next atom (overlaps compute below)
        if (a + 1 < g8 + 8) {
            const float* Xa = X   + ((size_t)b * AA + a + 1) * plane;
            const float* Ga = g_g + ((size_t)b * AA + a + 1) * plane;
            #pragma unroll
            for (int i = 0; i < 13; i++) {
                int e = tid + i * 128;
                if (e < 1600) {
                    int r = e / 40, c0 = e - r * 40;
                    int y = p0 - 8 + r, x = q0 - 8 + c0;
                    bool in = ((unsigned)y < (unsigned)HX) && ((unsigned)x < (unsigned)WX);
                    int o = in ? (y * WX + x) : 0;
                    unsigned sz = in ? 4u : 0u;
                    cpa4(stXa + 4u * e, Xa + o, sz);
                    cpa4(stGa + 4u * e, Ga + o, sz);
                }
            }
            cpa_commit();
        }

        // compute
        const float* w = Wd + a * 81;
        #pragma unroll 1
        for (int u = 0; u < 9; ++u) {
            unsigned long long wv2[9];
            #pragma unroll
            for (int v = 0; v < 9; ++v) {
                float wv = __ldg(w + u * 9 + v);
                wv2[v] = pk(wv, wv);
            }
            #pragma unroll
            for (int p = 0; p < 2; p++) {
                const ulonglong2* sp = (const ulonglong2*)(s[p] + (row + 8 - u) * S2 + cg * 8);
                unsigned long long win2[16];
                #pragma unroll
                for (int i = 0; i < 8; i++) {
                    ulonglong2 q = sp[i];
                    win2[2 * i]     = q.x;
                    win2[2 * i + 1] = q.y;
                }
                #pragma unroll
                for (int v = 0; v < 9; ++v) {
                    #pragma unroll
                    for (int j = 0; j < 8; ++j)
                        acc[p][j] = f2fma(wv2[v], win2[8 - v + j], acc[p][j]);
                }
            }
        }
    }

    size_t off = ((size_t)b * (HH * WW) + (p0 + row) * WW + q0 + cg * 8) >> 2;
    #pragma unroll
    for (int p = 0; p < 2; p++) {
        float2 e[8];
        #pragma unroll
        for (int j = 0; j < 8; j++) e[j] = upk(acc[p][j]);
        float4* dpa = (float4*)(g_Dpart) + (size_t)((2 * p) * 8 + group) * NY4 + off;
        dpa[0] = make_float4(e[0].x, e[1].x, e[2].x, e[3].x);
        dpa[1] = make_float4(e[4].x, e[5].x, e[6].x, e[7].x);
        float4* dpb = (float4*)(g_Dpart) + (size_t)((2 * p + 1) * 8 + group) * NY4 + off;
        dpb[0] = make_float4(e[0].y, e[1].y, e[2].y, e[3].y);
        dpb[1] = make_float4(e[4].y, e[5].y, e[6].y, e[7].y);
    }
    #pragma unroll
    for (int c = 0; c < 4; c++) {
        float t = blockReduce(l1[c], sb);
        if (tid == 0) g_pl1[c * 1024 + bid] = t;
    }
}

// ------------------------- scalar single-candidate conv ---------------------
template<int MODE>
__global__ void __launch_bounds__(128, 7) k_conv1(const float* __restrict__ X,
                                                  const float* __restrict__ Wd,
                                                  float a0)
{
    if (MODE && *((volatile int*)&g_done)) return;

    int bid   = blockIdx.x;
    int group = bid & 7;
    int tile  = (bid >> 3) & 15;
    int b     = bid >> 7;
    int p0 = (tile >> 2) * 32;
    int q0 = (tile & 3) * 32;
    int tid = threadIdx.x;
    int row = tid & 31;
    int cg  = tid >> 5;

    __shared__ float s[40 * 41];
    __shared__ float sb[32];

    float acc[8];
    #pragma unroll
    for (int j = 0; j < 8; j++) acc[j] = 0.f;
    float l1 = 0.f;
    const float ta0 = TAUF * a0;

    for (int a = group * 8; a < group * 8 + 8; ++a) {
        const float* Xa = X   + (size_t)(b * AA + a) * (HX * WX);
        const float* Ga = g_g + (size_t)(b * AA + a) * (HX * WX);
        __syncthreads();
        for (int e = tid; e < 1600; e += 128) {
            int r = e / 40, c = e - r * 40;
            int y = p0 - 8 + r, x = q0 - 8 + c;
            float v = 0.f;
            if ((unsigned)y < (unsigned)HX && (unsigned)x < (unsigned)WX) {
                float xv = Xa[y * WX + x];
                if (MODE) v = softt(fmaf(a0, Ga[y * WX + x], xv), ta0);
                else      v = xv;
                if (r >= 8 && c >= 8) l1 += fabsf(v);
            }
            s[r * 41 + c] = v;
        }
        __syncthreads();

        const float* w = Wd + a * 81;
        #pragma unroll
        for (int u = 0; u < 9; ++u) {
            float win[16];
            #pragma unroll
            for (int i = 0; i < 16; i++) win[i] = s[(row + 8 - u) * 41 + cg * 8 + i];
            #pragma unroll
            for (int v = 0; v < 9; ++v) {
                float wv = __ldg(w + u * 9 + v);
                #pragma unroll
                for (int j = 0; j < 8; j++) acc[j] = fmaf(wv, win[8 - v + j], acc[j]);
            }
        }
    }

    size_t off = ((size_t)b * (HH * WW) + (p0 + row) * WW + q0 + cg * 8) >> 2;
    float4* dp = (float4*)(g_Dpart) + (size_t)group * NY4 + off;
    dp[0] = make_float4(acc[0], acc[1], acc[2], acc[3]);
    dp[1] = make_float4(acc[4], acc[5], acc[6], acc[7]);

    float t = blockReduce(l1, sb);
    if (tid == 0) g_pl1[bid] = t;
}

// ------------------------- residual + cost + accept ------------------------
template<int NC>
__global__ void __launch_bounds__(256) k_red(const float* __restrict__ Y,
                                             int mode, int k,
                                             float a0, float a1, float a2, float a3)
{
    if (mode && *((volatile int*)&g_done)) return;
    int tid = threadIdx.x;
    int i4  = blockIdx.x * 256 + tid;

    const float4* Y4 = (const float4*)Y;
    const float4* DP = (const float4*)g_Dpart;
    float4 y = Y4[i4];

    float fid[NC];
    #pragma unroll
    for (int c = 0; c < NC; c++) {
        float4 d = make_float4(0.f, 0.f, 0.f, 0.f);
        #pragma unroll
        for (int gr = 0; gr < 8; ++gr) {
            float4 p = DP[(size_t)(c * 8 + gr) * NY4 + i4];
            d.x += p.x; d.y += p.y; d.z += p.z; d.w += p.w;
        }
        float4 r = make_float4(y.x - d.x, y.y - d.y, y.z - d.z, y.w - d.w);
        ((float4*)(g_R + (size_t)c * NY))[i4] = r;
        fid[c] = r.x * r.x + r.y * r.y + r.z * r.z + r.w * r.w;
    }

    __shared__ float sb[32];
    #pragma unroll
    for (int c = 0; c < NC; c++) {
        float t = blockReduce(fid[c], sb);
        if (tid == 0) g_pf[c * 128 + blockIdx.x] = t;
    }
    __threadfence();
    __shared__ bool last;
    if (tid == 0) last = (atomicAdd(&g_count, 1u) == gridDim.x - 1);
    __syncthreads();
    if (!last) return;

    float f[NC], l[NC];
    #pragma unroll
    for (int c = 0; c < NC; c++) {
        float v = (tid < 128) ? g_pf[c * 128 + tid] : 0.f;
        f[c] = blockReduce(v, sb);
        float lv = 0.f;
        for (int j = tid; j < 1024; j += 256) lv += g_pl1[c * 1024 + j];
        l[c] = blockReduce(lv, sb);
    }

    if (tid == 0) {
        g_count = 0;
        if (mode == 0) {
            g_cur_cost = f[0] + TAUF * l[0];
            g_l1X = l[0];
            g_done = 0;
            g_rsel = 0;
        } else {
            const float al[4] = {a0, a1, a2, a3};
            #pragma unroll
            for (int c = 0; c < NC; c++) {
                float cost = f[c] + TAUF * ((k + c == 0) ? g_l1X : l[c]);
                if ((k + c == 16) || cost < g_cur_cost) {
                    g_done = 1; g_rsel = c;
                    g_acc_alpha = al[c]; g_acc_fid = f[c];
                    break;
                }
            }
        }
    }
}

// ------------------------- g = Dt(R) ----------------------------------------
__global__ void __launch_bounds__(256, 2) k_dt(const float* __restrict__ Wd)
{
    int bid = blockIdx.x;
    int ct  = bid & 1;
    int rt  = (bid >> 1) & 3;
    int ag  = (bid >> 3) & 15;
    int b   = bid >> 7;
    int r0 = rt * 32, q0 = ct * 64;
    int tid = threadIdx.x;
    int row = tid & 31, cg = tid >> 5;

    __shared__ __align__(16) float s[40 * DSTR];
    const float* Rb = g_R + (size_t)g_rsel * NY + (size_t)b * (HH * WW);
    for (int e = tid; e < 40 * 72; e += 256) {
        int r = e / 72, c = e - r * 72;
        int rr = r0 + r, cc = q0 + c;
        s[r * DSTR + c] = (rr < HH && cc < WW) ? Rb[rr * WW + cc] : 0.f;
    }
    __syncthreads();

    int y  = r0 + row;
    int x0 = q0 + cg * 8;
    bool valid = (y < HX) && (x0 < WX);
    int abase = ag * 4;

    unsigned long long acc[4][4];
    #pragma unroll
    for (int a = 0; a < 4; a++)
        #pragma unroll
        for (int jp = 0; jp < 4; jp++) acc[a][jp] = 0ull;

    #pragma unroll 1
    for (int i = 0; i < 9; ++i) {
        const float4* sp4 = (const float4*)(s + (row + i) * DSTR + cg * 8);
        float4 A = sp4[0], B4 = sp4[1], C4 = sp4[2], D4 = sp4[3];
        float win[16] = {A.x, A.y, A.z, A.w, B4.x, B4.y, B4.z, B4.w,
                         C4.x, C4.y, C4.z, C4.w, D4.x, D4.y, D4.z, D4.w};
        unsigned long long P[15];
        #pragma unroll
        for (int t = 0; t < 15; t++) P[t] = pk(win[t], win[t + 1]);
        #pragma unroll
        for (int a = 0; a < 4; a++) {
            const float* w = Wd + (abase + a) * 81;
            #pragma unroll
            for (int j = 0; j < 9; ++j) {
                float wv = __ldg(w + j * 9 + i);
                unsigned long long wv2 = pk(wv, wv);
                #pragma unroll
                for (int jp = 0; jp < 4; ++jp)
                    acc[a][jp] = f2fma(wv2, P[j + 2 * jp], acc[a][jp]);
            }
        }
    }
    if (valid) {
        #pragma unroll
        for (int a = 0; a < 4; a++) {
            float* go = g_g + ((size_t)(b * AA + abase + a) * HX + y) * WX + x0;
            #pragma unroll
            for (int jp = 0; jp < 4; jp++) {
                float2 p = upk(acc[a][jp]);
                go[2 * jp] = p.x;
                go[2 * jp + 1] = p.y;
            }
        }
    }
}

// ------------------------- apply accepted step ------------------------------
__global__ void __launch_bounds__(256) k_apply(const float* __restrict__ Xsrc,
                                               float* __restrict__ Xdst)
{
    float alpha = g_acc_alpha;
    float ta = TAUF * alpha;
    float l1 = 0.f;
    int tid = threadIdx.x;
    const float4* Xs4 = (const float4*)Xsrc;
    const float4* G4  = (const float4*)g_g;
    float4* Xd4 = (float4*)Xdst;
    for (int i = blockIdx.x * 256 + tid; i < NX4; i += 1024 * 256) {
        float4 x = Xs4[i];
        float4 g = G4[i];
        float4 o;
        { float z = fmaf(alpha, g.x, x.x); float t = fabsf(z) - ta;
          o.x = (t > 0.f) ? copysignf(t, z) : 0.f; l1 += (t > 0.f) ? t : 0.f; }
        { float z = fmaf(alpha, g.y, x.y); float t = fabsf(z) - ta;
          o.y = (t > 0.f) ? copysignf(t, z) : 0.f; l1 += (t > 0.f) ? t : 0.f; }
        { float z = fmaf(alpha, g.z, x.z); float t = fabsf(z) - ta;
          o.z = (t > 0.f) ? copysignf(t, z) : 0.f; l1 += (t > 0.f) ? t : 0.f; }
        { float z = fmaf(alpha, g.w, x.w); float t = fabsf(z) - ta;
          o.w = (t > 0.f) ? copysignf(t, z) : 0.f; l1 += (t > 0.f) ? t : 0.f; }
        Xd4[i] = o;
    }
    __shared__ float sb[32];
    float tot = blockReduce(l1, sb);
    if (tid == 0) g_pl1x[blockIdx.x] = tot;
    __threadfence();
    __shared__ bool last;
    if (tid == 0) last = (atomicAdd(&g_count, 1u) == gridDim.x - 1);
    __syncthreads();
    if (!last) return;
    float l = 0.f;
    for (int j = tid; j < 1024; j += 256) l += g_pl1x[j];
    l = blockReduce(l, sb);
    if (tid == 0) {
        g_count = 0;
        g_cur_cost = g_acc_fid + TAUF * l;
        g_l1X = l;
        g_done = 0;
    }
}

// ------------------------- host launcher ------------------------------------
extern "C" void kernel_launch(void* const* d_in, const int* in_sizes, int n_in,
                              void* d_out, int out_size)
{
    const float* Y  = nullptr;
    const float* X1 = nullptr;
    const float* Wd = nullptr;
    for (int i = 0; i < n_in; i++) {
        if (in_sizes[i] == NY)      Y  = (const float*)d_in[i];
        else if (in_sizes[i] == NX) X1 = (const float*)d_in[i];
        else if (in_sizes[i] == NW) Wd = (const float*)d_in[i];
    }
    if (!Y)  Y  = (const float*)d_in[0];
    if (!X1) X1 = (const float*)d_in[1];
    if (!Wd) Wd = (const float*)d_in[2];

    float* X = (float*)d_out;

    for (int ls = 0; ls < 4; ++ls) {
        const float* Xin = (ls == 0) ? X1 : X;
        if (ls == 0) {
            k_conv1<0><<<1024, 128>>>(Xin, Wd, 0.f);
            k_red<1><<<128, 256>>>(Y, 0, -1, 0.f, 0.f, 0.f, 0.f);
        }
        k_dt<<<1024, 256>>>(Wd);
        for (int m = 0; m < 4; ++m) {
            float a0 = ldexpf(1.0f, -(4 * m));
            float a1 = ldexpf(1.0f, -(4 * m + 1));
            float a2 = ldexpf(1.0f, -(4 * m + 2));
            float a3 = ldexpf(1.0f, -(4 * m + 3));
            k_conv4<<<1024, 128>>>(Xin, Wd, a0, a1, a2, a3);
            k_red<4><<<128, 256>>>(Y, 1, 4 * m, a0, a1, a2, a3);
        }
        {
            float a16 = ldexpf(1.0f, -16);
            k_conv1<1><<<1024, 128>>>(Xin, Wd, a16);
            k_red<1><<<128, 256>>>(Y, 1, 16, a16, 0.f, 0.f, 0.f);
        }
        k_apply<<<1024, 256>>>(Xin, X);
    }
}